// round 13
// baseline (speedup 1.0000x reference)
#include <cuda_runtime.h>
#include <math.h>
#include <stdint.h>

// ---------------- problem constants ----------------
#define B_   2
#define S_   2048
#define D_   1024
#define HQ_  16
#define HKV_ 4
#define HD_  64
#define P_   4096
#define M_   (B_ * S_)        // 4096
#define KVD_ (HKV_ * HD_)     // 256

// ---------------- scratch ----------------
__device__ float g_h [M_ * D_];
__device__ float g_q [M_ * D_];
__device__ float g_k [M_ * KVD_];
__device__ float g_v [M_ * KVD_];
__device__ float g_o [M_ * D_];
__device__ float g_x2[M_ * D_];
__device__ float g_mid[M_ * P_];
// tf32-rounded, n-permuted weights (within each 128-col block)
__device__ float g_wq[D_ * D_];
__device__ float g_wk[D_ * KVD_];
__device__ float g_wv[D_ * KVD_];
__device__ float g_wo[D_ * D_];
__device__ float g_w1[D_ * P_];
__device__ float g_w2[P_ * D_];

__device__ __forceinline__ float to_tf32(float x) {
    float r; asm("cvt.rna.tf32.f32 %0, %1;" : "=f"(r) : "f"(x)); return r;
}

__device__ __forceinline__ void mma_tf32_16n8k8(
    float& d0, float& d1, float& d2, float& d3,
    uint32_t a0, uint32_t a1, uint32_t a2, uint32_t a3,
    uint32_t b0, uint32_t b1)
{
    asm volatile(
        "mma.sync.aligned.m16n8k8.row.col.f32.tf32.tf32.f32 "
        "{%0,%1,%2,%3}, {%4,%5,%6,%7}, {%8,%9}, {%0,%1,%2,%3};"
        : "+f"(d0), "+f"(d1), "+f"(d2), "+f"(d3)
        : "r"(a0), "r"(a1), "r"(a2), "r"(a3), "r"(b0), "r"(b1));
}

__device__ __forceinline__ void cp_async16(uint32_t s, const void* g) {
    asm volatile("cp.async.cg.shared.global [%0], [%1], 16;" :: "r"(s), "l"(g));
}
__device__ __forceinline__ void cp_commit() { asm volatile("cp.async.commit_group;" ::: "memory"); }
__device__ __forceinline__ void cp_wait0()  { asm volatile("cp.async.wait_group 0;" ::: "memory"); }
__device__ __forceinline__ void cp_wait1()  { asm volatile("cp.async.wait_group 1;" ::: "memory"); }

// ---------------- weight round + n-permute (single launch) ---------------
// dest j within 128-block: j = (n&7)*16 + (n>>3)  (so 8 cols/lane contiguous)
#define RW_N1 (D_ * D_ / 4)
#define RW_N2 (RW_N1 + D_ * KVD_ / 4)
#define RW_N3 (RW_N2 + D_ * KVD_ / 4)
#define RW_N4 (RW_N3 + D_ * D_ / 4)
#define RW_N5 (RW_N4 + D_ * P_ / 4)
#define RW_N6 (RW_N5 + P_ * D_ / 4)
__global__ __launch_bounds__(256) void round_all(
    const float* __restrict__ wq, const float* __restrict__ wk,
    const float* __restrict__ wv, const float* __restrict__ wo,
    const float* __restrict__ w1, const float* __restrict__ w2,
    float* __restrict__ rwq, float* __restrict__ rwk,
    float* __restrict__ rwv, float* __restrict__ rwo,
    float* __restrict__ rw1, float* __restrict__ rw2)
{
    int i = blockIdx.x * blockDim.x + threadIdx.x;   // dest float4 index
    if (i >= RW_N6) return;
    const float* s; float* d; int off, N;
    if      (i < RW_N1) { s = wq; d = rwq; off = 0;     N = D_; }
    else if (i < RW_N2) { s = wk; d = rwk; off = RW_N1; N = KVD_; }
    else if (i < RW_N3) { s = wv; d = rwv; off = RW_N2; N = KVD_; }
    else if (i < RW_N4) { s = wo; d = rwo; off = RW_N3; N = D_; }
    else if (i < RW_N5) { s = w1; d = rw1; off = RW_N4; N = P_; }
    else                { s = w2; d = rw2; off = RW_N5; N = P_ == 0 ? D_ : D_; }
    int j4 = i - off;                 // dest float4 within this weight
    int e0 = j4 * 4;                  // dest element
    int k  = e0 / N;
    int jc = e0 - k * N;              // dest col (permuted space)
    int nb = jc & ~127;
    int jl = jc & 127;                // 0..124, 4-aligned
    // inverse perm: n = (j&15)*8 + (j>>4); j,j+1,j+2,j+3 share j>>4 (jl%16<=12)
    int hi = jl >> 4;
    int lo = jl & 15;
    const float* sr = &s[(size_t)k * N + nb];
    float4 v;
    v.x = to_tf32(sr[(lo + 0) * 8 + hi]);
    v.y = to_tf32(sr[(lo + 1) * 8 + hi]);
    v.z = to_tf32(sr[(lo + 2) * 8 + hi]);
    v.w = to_tf32(sr[(lo + 3) * 8 + hi]);
    *(float4*)&d[(size_t)e0] = v;
}

// ---------------- LayerNorm (tf32-rounded output) ----------------
__global__ __launch_bounds__(256) void ln_kernel(
    const float* __restrict__ x, const float* __restrict__ gam,
    const float* __restrict__ bet, float* __restrict__ out)
{
    __shared__ float red[20];
    int row = blockIdx.x;
    int tid = threadIdx.x;
    const float* xr = x + (size_t)row * D_;
    float4 v = *(const float4*)&xr[tid * 4];
    float s  = v.x + v.y + v.z + v.w;
    float sq = v.x * v.x + v.y * v.y + v.z * v.z + v.w * v.w;
    #pragma unroll
    for (int o = 16; o; o >>= 1) {
        s  += __shfl_xor_sync(0xffffffffu, s,  o);
        sq += __shfl_xor_sync(0xffffffffu, sq, o);
    }
    if ((tid & 31) == 0) { red[tid >> 5] = s; red[8 + (tid >> 5)] = sq; }
    __syncthreads();
    if (tid < 32) {
        float a = (tid < 8) ? red[tid]     : 0.f;
        float b = (tid < 8) ? red[8 + tid] : 0.f;
        #pragma unroll
        for (int o = 4; o; o >>= 1) {
            a += __shfl_xor_sync(0xffffffffu, a, o);
            b += __shfl_xor_sync(0xffffffffu, b, o);
        }
        if (tid == 0) { red[16] = a; red[17] = b; }
    }
    __syncthreads();
    float mean = red[16] * (1.f / D_);
    float var  = red[17] * (1.f / D_) - mean * mean;
    float rs   = rsqrtf(var + 1e-5f);
    float4 gv = *(const float4*)&gam[tid * 4];
    float4 bv = *(const float4*)&bet[tid * 4];
    float4 ov;
    ov.x = to_tf32((v.x - mean) * rs * gv.x + bv.x);
    ov.y = to_tf32((v.y - mean) * rs * gv.y + bv.y);
    ov.z = to_tf32((v.z - mean) * rs * gv.z + bv.z);
    ov.w = to_tf32((v.w - mean) * rs * gv.w + bv.w);
    *(float4*)&out[(size_t)row * D_ + tid * 4] = ov;
}

// ---------------- RoPE: 256-thread blocks, flat index -------------------
__global__ __launch_bounds__(256) void rope_kernel(
    float* __restrict__ buf, int nheads, float scale)
{
    int i = blockIdx.x * blockDim.x + threadIdx.x;
    int j = i & 31;
    int h = (i >> 5) % nheads;
    int t = i / (32 * nheads);
    int s = t & (S_ - 1);
    float inv = exp2f(-(float)j * (13.287712379549449f / 32.0f));
    float ang = (float)s * inv;
    float sn, c;
    sincosf(ang, &sn, &c);
    float* p = buf + (size_t)t * (nheads * HD_) + h * HD_;
    float x1 = p[j], x2 = p[j + 32];
    p[j]      = to_tf32((x1 * c - x2 * sn) * scale);
    p[j + 32] = to_tf32((x1 * sn + x2 * c) * scale);
}

// ---------------- cp.async 3-stage tf32 GEMM, n-permuted B --------------
#define TBM 128
#define TBN 128
#define TBK 32
#define ASTR 36
#define BSTR 132
#define ASZ (TBM * ASTR)
#define BSZ (TBK * BSTR)
#define STG (ASZ + BSZ)
#define GEMM_SMEM (3 * STG * 4)    // 106368 B

enum { EPI_NONE = 0, EPI_RES = 1, EPI_BIAS_GELU = 2, EPI_BIAS_RES = 3, EPI_ROUND = 4 };

template <int EPI>
__device__ __forceinline__ void gemm_body(
    const float* __restrict__ A, const float* __restrict__ Bm,
    const float* __restrict__ bias, const float* __restrict__ res,
    float* __restrict__ C, int M, int N, int K, int m0, int n0, float* sm)
{
    int tid = threadIdx.x;
    int wid = tid >> 5, lane = tid & 31;
    int g = lane >> 2, tg = lane & 3;
    int wm = (wid & 3) * 32, wn = (wid >> 2) * 64;
    int wnq = wn >> 3;                    // 0 or 8
    uint32_t smb = (uint32_t)__cvta_generic_to_shared(sm);

    auto issue = [&](int kc, int st) {
        int k0 = kc * TBK;
        uint32_t ab = smb + (uint32_t)(st * STG) * 4u;
        uint32_t bb = ab + ASZ * 4u;
        #pragma unroll
        for (int t = 0; t < 4; t++) {
            int i = tid + 256 * t;
            int mm = i >> 3, kq = i & 7;
            cp_async16(ab + (uint32_t)(mm * ASTR + kq * 4) * 4u,
                       &A[(size_t)(m0 + mm) * K + k0 + kq * 4]);
            int kk = i >> 5, nq = i & 31;
            cp_async16(bb + (uint32_t)(kk * BSTR + nq * 4) * 4u,
                       &Bm[(size_t)(k0 + kk) * N + n0 + nq * 4]);
        }
        cp_commit();
    };

    float c[2][8][4];
    #pragma unroll
    for (int mi = 0; mi < 2; mi++)
        #pragma unroll
        for (int ni = 0; ni < 8; ni++)
            #pragma unroll
            for (int e = 0; e < 4; e++) c[mi][ni][e] = 0.f;

    int nch = K / TBK;
    issue(0, 0);
    issue(1, 1);

    for (int cc = 0; cc < nch; cc++) {
        if (cc + 1 < nch) cp_wait1(); else cp_wait0();
        __syncthreads();
        if (cc + 2 < nch) issue(cc + 2, (cc + 2) % 3);
        float* As = sm + (cc % 3) * STG;
        float* Bs = As + ASZ;
        #pragma unroll
        for (int ks = 0; ks < 4; ks++) {
            int k0 = ks * 8;
            uint32_t a[2][4];
            #pragma unroll
            for (int mi = 0; mi < 2; mi++) {
                int rb = wm + mi * 16;
                a[mi][0] = __float_as_uint(As[(rb + g)     * ASTR + k0 + tg]);
                a[mi][1] = __float_as_uint(As[(rb + g + 8) * ASTR + k0 + tg]);
                a[mi][2] = __float_as_uint(As[(rb + g)     * ASTR + k0 + tg + 4]);
                a[mi][3] = __float_as_uint(As[(rb + g + 8) * ASTR + k0 + tg + 4]);
            }
            // B fragments: permuted layout -> 4x LDS.128 per k-step
            float4 bA = *(float4*)&Bs[(k0 + tg)     * BSTR + g * 16 + wnq];
            float4 bB = *(float4*)&Bs[(k0 + tg)     * BSTR + g * 16 + wnq + 4];
            float4 bC = *(float4*)&Bs[(k0 + tg + 4) * BSTR + g * 16 + wnq];
            float4 bD = *(float4*)&Bs[(k0 + tg + 4) * BSTR + g * 16 + wnq + 4];
            uint32_t b[8][2];
            b[0][0] = __float_as_uint(bA.x); b[1][0] = __float_as_uint(bA.y);
            b[2][0] = __float_as_uint(bA.z); b[3][0] = __float_as_uint(bA.w);
            b[4][0] = __float_as_uint(bB.x); b[5][0] = __float_as_uint(bB.y);
            b[6][0] = __float_as_uint(bB.z); b[7][0] = __float_as_uint(bB.w);
            b[0][1] = __float_as_uint(bC.x); b[1][1] = __float_as_uint(bC.y);
            b[2][1] = __float_as_uint(bC.z); b[3][1] = __float_as_uint(bC.w);
            b[4][1] = __float_as_uint(bD.x); b[5][1] = __float_as_uint(bD.y);
            b[6][1] = __float_as_uint(bD.z); b[7][1] = __float_as_uint(bD.w);
            #pragma unroll
            for (int mi = 0; mi < 2; mi++)
                #pragma unroll
                for (int ni = 0; ni < 8; ni++)
                    mma_tf32_16n8k8(c[mi][ni][0], c[mi][ni][1], c[mi][ni][2], c[mi][ni][3],
                                    a[mi][0], a[mi][1], a[mi][2], a[mi][3],
                                    b[ni][0], b[ni][1]);
        }
        __syncthreads();
    }

    #pragma unroll
    for (int mi = 0; mi < 2; mi++) {
        #pragma unroll
        for (int ni = 0; ni < 8; ni++) {
            int ccol = n0 + wn + ni * 8 + 2 * tg;
            #pragma unroll
            for (int hr = 0; hr < 2; hr++) {
                int r = m0 + wm + mi * 16 + g + hr * 8;
                float v0 = c[mi][ni][hr * 2 + 0];
                float v1 = c[mi][ni][hr * 2 + 1];
                size_t idx = (size_t)r * N + ccol;
                if (EPI == EPI_RES) { v0 += res[idx]; v1 += res[idx + 1]; }
                if (EPI == EPI_BIAS_GELU) {
                    float u0 = v0 + bias[ccol], u1 = v1 + bias[ccol + 1];
                    float z0 = 1.5957691216057308f * (u0 + 0.044715f * u0 * u0 * u0);
                    float z1 = 1.5957691216057308f * (u1 + 0.044715f * u1 * u1 * u1);
                    v0 = to_tf32(__fdividef(u0, 1.f + __expf(-z0)));
                    v1 = to_tf32(__fdividef(u1, 1.f + __expf(-z1)));
                }
                if (EPI == EPI_BIAS_RES) {
                    v0 += bias[ccol]     + res[idx];
                    v1 += bias[ccol + 1] + res[idx + 1];
                }
                if (EPI == EPI_ROUND) { v0 = to_tf32(v0); v1 = to_tf32(v1); }
                *(float2*)&C[idx] = make_float2(v0, v1);
            }
        }
    }
}

template <int EPI>
__global__ __launch_bounds__(256) void gemm_mma(
    const float* __restrict__ A, const float* __restrict__ Bm,
    const float* __restrict__ bias, const float* __restrict__ res,
    float* __restrict__ C, int M, int N, int K)
{
    extern __shared__ float sm[];
    gemm_body<EPI>(A, Bm, bias, res, C, M, N, K,
                   blockIdx.y * TBM, blockIdx.x * TBN, sm);
}

// fused QKV: grid (12, 32). bx<8 -> wq, bx 8-9 -> wk, bx 10-11 -> wv.
__global__ __launch_bounds__(256) void qkv_gemm(
    const float* __restrict__ h,
    const float* __restrict__ wq, const float* __restrict__ wk, const float* __restrict__ wv,
    float* __restrict__ q, float* __restrict__ k, float* __restrict__ v)
{
    extern __shared__ float sm[];
    int bx = blockIdx.x;
    const float* Bm; float* C; int N, n0;
    if (bx < 8)       { Bm = wq; C = q; N = D_;   n0 = bx * 128; }
    else if (bx < 10) { Bm = wk; C = k; N = KVD_; n0 = (bx - 8) * 128; }
    else              { Bm = wv; C = v; N = KVD_; n0 = (bx - 10) * 128; }
    gemm_body<EPI_ROUND>(h, Bm, nullptr, nullptr, C, M_, N, D_,
                         blockIdx.y * TBM, n0, sm);
}

// ---------------- tensor-core causal flash attention (R11 config) -------
#define AQB 128
#define ACB 64
#define KVS 68
#define KVSTG (2 * ACB * KVS)
#define ATTN_SMEM ((2 * KVSTG + 8 * 16 * KVS) * 4)   // 104448 B

__global__ __launch_bounds__(256) void attn_tc(
    const float* __restrict__ Q, const float* __restrict__ Kg,
    const float* __restrict__ Vg, float* __restrict__ O)
{
    extern __shared__ float sm[];
    float* Ps = sm + 2 * KVSTG;

    int tid = threadIdx.x, w = tid >> 5, lane = tid & 31;
    int g = lane >> 2, tg = lane & 3;
    int bx = blockIdx.x, hq = blockIdx.y, b = blockIdx.z;
    int kvh = hq & (HKV_ - 1);
    float* Pw = Ps + w * 16 * KVS;
    uint32_t smb = (uint32_t)__cvta_generic_to_shared(sm);

    int qts[2] = {15 - bx, bx};
    int nts[2] = {2 * (15 - bx) + 2, 2 * bx + 2};
    int total = nts[0] + nts[1];

    auto issue_kv = [&](int i, int st) {
        int kvt = (i < nts[0]) ? i : i - nts[0];
        int kv0 = kvt * ACB;
        uint32_t base = smb + (uint32_t)(st * KVSTG) * 4u;
        #pragma unroll
        for (int t = 0; t < 4; t++) {
            int s = tid + 256 * t;
            int kv = s >> 4, hd4 = (s & 15) * 4;
            size_t gidx = ((size_t)(b * S_ + kv0 + kv)) * KVD_ + kvh * HD_ + hd4;
            cp_async16(base + (uint32_t)(kv * KVS + hd4) * 4u, &Kg[gidx]);
            cp_async16(base + (uint32_t)((ACB + kv) * KVS + hd4) * 4u, &Vg[gidx]);
        }
        cp_commit();
    };

    uint32_t qf[8][4];
    float oc[8][4];
    float m0r, m1r, l0, l1;
    int q0 = qts[0] * AQB;
    int wrow = q0 + w * 16;

    auto load_q = [&]() {
        const float* Qb = Q + ((size_t)(b * S_ + wrow)) * D_ + hq * HD_;
        #pragma unroll
        for (int ks = 0; ks < 8; ks++) {
            qf[ks][0] = __float_as_uint(Qb[(size_t)g       * D_ + ks * 8 + tg]);
            qf[ks][1] = __float_as_uint(Qb[(size_t)(g + 8) * D_ + ks * 8 + tg]);
            qf[ks][2] = __float_as_uint(Qb[(size_t)g       * D_ + ks * 8 + tg + 4]);
            qf[ks][3] = __float_as_uint(Qb[(size_t)(g + 8) * D_ + ks * 8 + tg + 4]);
        }
    };
    auto reset_acc = [&]() {
        #pragma unroll
        for (int ni = 0; ni < 8; ni++)
            #pragma unroll
            for (int e = 0; e < 4; e++) oc[ni][e] = 0.f;
        m0r = -1e30f; m1r = -1e30f; l0 = 0.f; l1 = 0.f;
    };
    auto epilogue = [&]() {
        float il0 = 1.f / l0, il1 = 1.f / l1;
        size_t ob0 = ((size_t)(b * S_ + wrow + g))     * D_ + hq * HD_;
        size_t ob1 = ((size_t)(b * S_ + wrow + g + 8)) * D_ + hq * HD_;
        #pragma unroll
        for (int ni = 0; ni < 8; ni++) {
            int cc = ni * 8 + 2 * tg;
            *(float2*)&O[ob0 + cc] = make_float2(to_tf32(oc[ni][0] * il0), to_tf32(oc[ni][1] * il0));
            *(float2*)&O[ob1 + cc] = make_float2(to_tf32(oc[ni][2] * il1), to_tf32(oc[ni][3] * il1));
        }
    };

    load_q();
    reset_acc();
    issue_kv(0, 0);

    for (int i = 0; i < total; i++) {
        if (i + 1 < total) issue_kv(i + 1, (i + 1) & 1);
        if (i + 1 < total) cp_wait1(); else cp_wait0();
        __syncthreads();

        int kvt = (i < nts[0]) ? i : i - nts[0];
        int kv0 = kvt * ACB;
        float* Ks = sm + (i & 1) * KVSTG;
        float* Vs = Ks + ACB * KVS;

        bool active = (kv0 <= wrow + 15);
        if (active) {
            float sc[8][4];
            #pragma unroll
            for (int ni = 0; ni < 8; ni++)
                #pragma unroll
                for (int e = 0; e < 4; e++) sc[ni][e] = 0.f;
            #pragma unroll
            for (int ks = 0; ks < 8; ks++) {
                #pragma unroll
                for (int ni = 0; ni < 8; ni++) {
                    uint32_t b0 = __float_as_uint(Ks[(ni * 8 + g) * KVS + ks * 8 + tg]);
                    uint32_t b1 = __float_as_uint(Ks[(ni * 8 + g) * KVS + ks * 8 + tg + 4]);
                    mma_tf32_16n8k8(sc[ni][0], sc[ni][1], sc[ni][2], sc[ni][3],
                                    qf[ks][0], qf[ks][1], qf[ks][2], qf[ks][3], b0, b1);
                }
            }
            bool diag = (kv0 + ACB > wrow);
            int r0 = wrow + g, r1 = wrow + g + 8;
            if (diag) {
                #pragma unroll
                for (int ni = 0; ni < 8; ni++) {
                    int c0 = kv0 + ni * 8 + 2 * tg, c1 = c0 + 1;
                    if (c0 > r0) sc[ni][0] = -1e9f;
                    if (c1 > r0) sc[ni][1] = -1e9f;
                    if (c0 > r1) sc[ni][2] = -1e9f;
                    if (c1 > r1) sc[ni][3] = -1e9f;
                }
            }
            float tm0 = -1e30f, tm1 = -1e30f;
            #pragma unroll
            for (int ni = 0; ni < 8; ni++) {
                tm0 = fmaxf(tm0, fmaxf(sc[ni][0], sc[ni][1]));
                tm1 = fmaxf(tm1, fmaxf(sc[ni][2], sc[ni][3]));
            }
            #pragma unroll
            for (int o = 1; o <= 2; o <<= 1) {
                tm0 = fmaxf(tm0, __shfl_xor_sync(0xffffffffu, tm0, o));
                tm1 = fmaxf(tm1, __shfl_xor_sync(0xffffffffu, tm1, o));
            }
            float mn0 = fmaxf(m0r, tm0), mn1 = fmaxf(m1r, tm1);
            float corr0 = __expf(m0r - mn0), corr1 = __expf(m1r - mn1);
            float ps0 = 0.f, ps1 = 0.f;
            #pragma unroll
            for (int ni = 0; ni < 8; ni++) {
                float p0 = __expf(sc[ni][0] - mn0);
                float p1 = __expf(sc[ni][1] - mn0);
                float p2 = __expf(sc[ni][2] - mn1);
                float p3 = __expf(sc[ni][3] - mn1);
                ps0 += p0 + p1; ps1 += p2 + p3;
                int cc = ni * 8 + 2 * tg;
                *(float2*)&Pw[g * KVS + cc]       = make_float2(to_tf32(p0), to_tf32(p1));
                *(float2*)&Pw[(g + 8) * KVS + cc] = make_float2(to_tf32(p2), to_tf32(p3));
            }
            #pragma unroll
            for (int o = 1; o <= 2; o <<= 1) {
                ps0 += __shfl_xor_sync(0xffffffffu, ps0, o);
                ps1 += __shfl_xor_sync(0xffffffffu, ps1, o);
            }
            l0 = l0 * corr0 + ps0; l1 = l1 * corr1 + ps1;
            m0r = mn0; m1r = mn1;
            #pragma unroll
            for (int ni = 0; ni < 8; ni++) {
                oc[ni][0] *= corr0; oc[ni][1] *= corr0;
                oc[ni][2] *= corr1; oc[ni][3] *= corr1;
            }
            __syncwarp();
            #pragma unroll
            for (int ks = 0; ks < 8; ks++) {
                uint32_t a0 = __float_as_uint(Pw[g       * KVS + ks * 8 + tg]);
                uint32_t a1 = __float_as_uint(Pw[(g + 8) * KVS + ks * 8 + tg]);
                uint32_t a2 = __float_as_uint(Pw[g       * KVS + ks * 8 + tg + 4]);
                uint32_t a3 = __float_as_uint(Pw[(g + 8) * KVS + ks * 8 + tg + 4]);
                #pragma unroll
                for (int ni = 0; ni < 8; ni++) {
                    uint32_t b0 = __float_as_uint(Vs[(ks * 8 + tg)     * KVS + ni * 8 + g]);
                    uint32_t b1 = __float_as_uint(Vs[(ks * 8 + tg + 4) * KVS + ni * 8 + g]);
                    mma_tf32_16n8k8(oc[ni][0], oc[ni][1], oc[ni][2], oc[ni][3],
                                    a0, a1, a2, a3, b0, b1);
                }
            }
        }
        __syncthreads();

        if (i == nts[0] - 1) {
            epilogue();
            q0 = qts[1] * AQB;
            wrow = q0 + w * 16;
            load_q();
            reset_acc();
        } else if (i == total - 1) {
            epilogue();
        }
    }
}

// ---------------- launch ----------------
extern "C" void kernel_launch(void* const* d_in, const int* in_sizes, int n_in,
                              void* d_out, int out_size)
{
    const float* x    = (const float*)d_in[0];
    const float* wq   = (const float*)d_in[2];
    const float* wk   = (const float*)d_in[3];
    const float* wv   = (const float*)d_in[4];
    const float* wo   = (const float*)d_in[5];
    const float* ln1g = (const float*)d_in[6];
    const float* ln1b = (const float*)d_in[7];
    const float* ln2g = (const float*)d_in[8];
    const float* ln2b = (const float*)d_in[9];
    const float* w1   = (const float*)d_in[10];
    const float* b1   = (const float*)d_in[11];
    const float* w2   = (const float*)d_in[12];
    const float* b2   = (const float*)d_in[13];
    float* out = (float*)d_out;

    float *h, *q, *k, *v, *o, *x2, *mid;
    float *rwq, *rwk, *rwv, *rwo, *rw1, *rw2;
    cudaGetSymbolAddress((void**)&h,   g_h);
    cudaGetSymbolAddress((void**)&q,   g_q);
    cudaGetSymbolAddress((void**)&k,   g_k);
    cudaGetSymbolAddress((void**)&v,   g_v);
    cudaGetSymbolAddress((void**)&o,   g_o);
    cudaGetSymbolAddress((void**)&x2,  g_x2);
    cudaGetSymbolAddress((void**)&mid, g_mid);
    cudaGetSymbolAddress((void**)&rwq, g_wq);
    cudaGetSymbolAddress((void**)&rwk, g_wk);
    cudaGetSymbolAddress((void**)&rwv, g_wv);
    cudaGetSymbolAddress((void**)&rwo, g_wo);
    cudaGetSymbolAddress((void**)&rw1, g_w1);
    cudaGetSymbolAddress((void**)&rw2, g_w2);

    cudaFuncSetAttribute(attn_tc,  cudaFuncAttributeMaxDynamicSharedMemorySize, ATTN_SMEM);
    cudaFuncSetAttribute(qkv_gemm, cudaFuncAttributeMaxDynamicSharedMemorySize, GEMM_SMEM);
    cudaFuncSetAttribute(gemm_mma<EPI_RES>,       cudaFuncAttributeMaxDynamicSharedMemorySize, GEMM_SMEM);
    cudaFuncSetAttribute(gemm_mma<EPI_BIAS_GELU>, cudaFuncAttributeMaxDynamicSharedMemorySize, GEMM_SMEM);
    cudaFuncSetAttribute(gemm_mma<EPI_BIAS_RES>,  cudaFuncAttributeMaxDynamicSharedMemorySize, GEMM_SMEM);

    // 0. round + n-permute all weights (single launch)
    round_all<<<(RW_N6 + 255) / 256, 256>>>(wq, wk, wv, wo, w1, w2,
                                            rwq, rwk, rwv, rwo, rw1, rw2);

    // 1. h = LN1(x)
    ln_kernel<<<M_, 256>>>(x, ln1g, ln1b, h);
    // 2. fused q/k/v projection
    qkv_gemm<<<dim3(12, M_ / TBM), 256, GEMM_SMEM>>>(h, rwq, rwk, rwv, q, k, v);
    // 3-4. RoPE (q folds 1/8 scale)
    rope_kernel<<<(M_ * HQ_ * 32) / 256,  256>>>(q, HQ_, 0.125f);
    rope_kernel<<<(M_ * HKV_ * 32) / 256, 256>>>(k, HKV_, 1.0f);
    // 5. attention (R11 config)
    attn_tc<<<dim3(8, HQ_, B_), 256, ATTN_SMEM>>>(q, k, v, o);
    // 6. x2 = x + o @ wo
    gemm_mma<EPI_RES><<<dim3(D_ / TBN, M_ / TBM), 256, GEMM_SMEM>>>(o, rwo, nullptr, x, x2, M_, D_, D_);
    // 7. h2 = LN2(x2)
    ln_kernel<<<M_, 256>>>(x2, ln2g, ln2b, h);
    // 8. mid = gelu(h2 @ w1 + b1)
    gemm_mma<EPI_BIAS_GELU><<<dim3(P_ / TBN, M_ / TBM), 256, GEMM_SMEM>>>(h, rw1, b1, nullptr, mid, M_, P_, D_);
    // 9. out = x2 + mid @ w2 + b2
    gemm_mma<EPI_BIAS_RES><<<dim3(D_ / TBN, M_ / TBM), 256, GEMM_SMEM>>>(mid, rw2, b2, x2, out, M_, D_, P_);
}

// round 15
// speedup vs baseline: 1.1652x; 1.1652x over previous
#include <cuda_runtime.h>
#include <math.h>
#include <stdint.h>

// ---------------- problem constants ----------------
#define B_   2
#define S_   2048
#define D_   1024
#define HQ_  16
#define HKV_ 4
#define HD_  64
#define P_   4096
#define M_   (B_ * S_)        // 4096
#define KVD_ (HKV_ * HD_)     // 256

// ---------------- scratch ----------------
__device__ float g_h [M_ * D_];
__device__ float g_q [M_ * D_];
__device__ float g_k [M_ * KVD_];
__device__ float g_v [M_ * KVD_];
__device__ float g_o [M_ * D_];
__device__ float g_x2[M_ * D_];
__device__ float g_mid[M_ * P_];
// tf32-rounded weights
__device__ float g_wq[D_ * D_];
__device__ float g_wk[D_ * KVD_];
__device__ float g_wv[D_ * KVD_];
__device__ float g_wo[D_ * D_];
__device__ float g_w1[D_ * P_];
__device__ float g_w2[P_ * D_];

__device__ __forceinline__ float to_tf32(float x) {
    float r; asm("cvt.rna.tf32.f32 %0, %1;" : "=f"(r) : "f"(x)); return r;
}

__device__ __forceinline__ void mma_tf32_16n8k8(
    float& d0, float& d1, float& d2, float& d3,
    uint32_t a0, uint32_t a1, uint32_t a2, uint32_t a3,
    uint32_t b0, uint32_t b1)
{
    asm volatile(
        "mma.sync.aligned.m16n8k8.row.col.f32.tf32.tf32.f32 "
        "{%0,%1,%2,%3}, {%4,%5,%6,%7}, {%8,%9}, {%0,%1,%2,%3};"
        : "+f"(d0), "+f"(d1), "+f"(d2), "+f"(d3)
        : "r"(a0), "r"(a1), "r"(a2), "r"(a3), "r"(b0), "r"(b1));
}

__device__ __forceinline__ void cp_async16(uint32_t s, const void* g) {
    asm volatile("cp.async.cg.shared.global [%0], [%1], 16;" :: "r"(s), "l"(g));
}
__device__ __forceinline__ void cp_commit() { asm volatile("cp.async.commit_group;" ::: "memory"); }
__device__ __forceinline__ void cp_wait0()  { asm volatile("cp.async.wait_group 0;" ::: "memory"); }
__device__ __forceinline__ void cp_wait1()  { asm volatile("cp.async.wait_group 1;" ::: "memory"); }

// ---------------- weight rounding: single launch over all 6 weights -----
#define RW_N1 (D_ * D_ / 4)
#define RW_N2 (RW_N1 + D_ * KVD_ / 4)
#define RW_N3 (RW_N2 + D_ * KVD_ / 4)
#define RW_N4 (RW_N3 + D_ * D_ / 4)
#define RW_N5 (RW_N4 + D_ * P_ / 4)
#define RW_N6 (RW_N5 + P_ * D_ / 4)
__global__ __launch_bounds__(256) void round_all(
    const float* __restrict__ wq, const float* __restrict__ wk,
    const float* __restrict__ wv, const float* __restrict__ wo,
    const float* __restrict__ w1, const float* __restrict__ w2,
    float* __restrict__ rwq, float* __restrict__ rwk,
    float* __restrict__ rwv, float* __restrict__ rwo,
    float* __restrict__ rw1, float* __restrict__ rw2)
{
    int i = blockIdx.x * blockDim.x + threadIdx.x;
    if (i >= RW_N6) return;
    const float* s; float* d; int off;
    if      (i < RW_N1) { s = wq; d = rwq; off = 0; }
    else if (i < RW_N2) { s = wk; d = rwk; off = RW_N1; }
    else if (i < RW_N3) { s = wv; d = rwv; off = RW_N2; }
    else if (i < RW_N4) { s = wo; d = rwo; off = RW_N3; }
    else if (i < RW_N5) { s = w1; d = rw1; off = RW_N4; }
    else                { s = w2; d = rw2; off = RW_N5; }
    int j = i - off;
    float4 v = *(const float4*)&s[(size_t)j * 4];
    v.x = to_tf32(v.x); v.y = to_tf32(v.y); v.z = to_tf32(v.z); v.w = to_tf32(v.w);
    *(float4*)&d[(size_t)j * 4] = v;
}

// ---------------- LayerNorm (tf32-rounded output) ----------------
__global__ __launch_bounds__(256) void ln_kernel(
    const float* __restrict__ x, const float* __restrict__ gam,
    const float* __restrict__ bet, float* __restrict__ out)
{
    __shared__ float red[20];
    int row = blockIdx.x;
    int tid = threadIdx.x;
    const float* xr = x + (size_t)row * D_;
    float4 v = *(const float4*)&xr[tid * 4];
    float s  = v.x + v.y + v.z + v.w;
    float sq = v.x * v.x + v.y * v.y + v.z * v.z + v.w * v.w;
    #pragma unroll
    for (int o = 16; o; o >>= 1) {
        s  += __shfl_xor_sync(0xffffffffu, s,  o);
        sq += __shfl_xor_sync(0xffffffffu, sq, o);
    }
    if ((tid & 31) == 0) { red[tid >> 5] = s; red[8 + (tid >> 5)] = sq; }
    __syncthreads();
    if (tid < 32) {
        float a = (tid < 8) ? red[tid]     : 0.f;
        float b = (tid < 8) ? red[8 + tid] : 0.f;
        #pragma unroll
        for (int o = 4; o; o >>= 1) {
            a += __shfl_xor_sync(0xffffffffu, a, o);
            b += __shfl_xor_sync(0xffffffffu, b, o);
        }
        if (tid == 0) { red[16] = a; red[17] = b; }
    }
    __syncthreads();
    float mean = red[16] * (1.f / D_);
    float var  = red[17] * (1.f / D_) - mean * mean;
    float rs   = rsqrtf(var + 1e-5f);
    float4 gv = *(const float4*)&gam[tid * 4];
    float4 bv = *(const float4*)&bet[tid * 4];
    float4 ov;
    ov.x = to_tf32((v.x - mean) * rs * gv.x + bv.x);
    ov.y = to_tf32((v.y - mean) * rs * gv.y + bv.y);
    ov.z = to_tf32((v.z - mean) * rs * gv.z + bv.z);
    ov.w = to_tf32((v.w - mean) * rs * gv.w + bv.w);
    *(float4*)&out[(size_t)row * D_ + tid * 4] = ov;
}

// ---------------- fused RoPE (q then k), single launch ------------------
// q items: M_*HQ_*32 (scale 1/8). k items: M_*HKV_*32 (scale 1).
#define NQI (M_ * HQ_ * 32)
#define NKI (M_ * HKV_ * 32)
__global__ __launch_bounds__(256) void rope_fused(
    float* __restrict__ qb, float* __restrict__ kb)
{
    int i = blockIdx.x * blockDim.x + threadIdx.x;
    float* buf; int nheads; float scale;
    if (i < NQI) { buf = qb; nheads = HQ_; scale = 0.125f; }
    else         { buf = kb; nheads = HKV_; scale = 1.0f; i -= NQI; }
    int j = i & 31;
    int h = (i >> 5) % nheads;
    int t = i / (32 * nheads);
    int s = t & (S_ - 1);
    float inv = exp2f(-(float)j * (13.287712379549449f / 32.0f));
    float ang = (float)s * inv;
    float sn, c;
    sincosf(ang, &sn, &c);
    float* p = buf + (size_t)t * (nheads * HD_) + h * HD_;
    float x1 = p[j], x2 = p[j + 32];
    p[j]      = to_tf32((x1 * c - x2 * sn) * scale);
    p[j + 32] = to_tf32((x1 * sn + x2 * c) * scale);
}

// ---------------- cp.async 3-stage tf32 GEMM (R8 config, frozen) --------
#define TBM 128
#define TBN 128
#define TBK 32
#define ASTR 36
#define BSTR 136
#define ASZ (TBM * ASTR)
#define BSZ (TBK * BSTR)
#define STG (ASZ + BSZ)
#define GEMM_SMEM (3 * STG * 4)    // 107520 B

enum { EPI_NONE = 0, EPI_RES = 1, EPI_BIAS_GELU = 2, EPI_BIAS_RES = 3, EPI_ROUND = 4 };

template <int EPI>
__device__ __forceinline__ void gemm_body(
    const float* __restrict__ A, const float* __restrict__ Bm,
    const float* __restrict__ bias, const float* __restrict__ res,
    float* __restrict__ C, int M, int N, int K, int m0, int n0, float* sm)
{
    int tid = threadIdx.x;
    int wid = tid >> 5, lane = tid & 31;
    int g = lane >> 2, tg = lane & 3;
    int wm = (wid & 3) * 32, wn = (wid >> 2) * 64;
    uint32_t smb = (uint32_t)__cvta_generic_to_shared(sm);

    auto issue = [&](int kc, int st) {
        int k0 = kc * TBK;
        uint32_t ab = smb + (uint32_t)(st * STG) * 4u;
        uint32_t bb = ab + ASZ * 4u;
        #pragma unroll
        for (int t = 0; t < 4; t++) {
            int i = tid + 256 * t;
            int mm = i >> 3, kq = i & 7;
            cp_async16(ab + (uint32_t)(mm * ASTR + kq * 4) * 4u,
                       &A[(size_t)(m0 + mm) * K + k0 + kq * 4]);
            int kk = i >> 5, nq = i & 31;
            cp_async16(bb + (uint32_t)(kk * BSTR + nq * 4) * 4u,
                       &Bm[(size_t)(k0 + kk) * N + n0 + nq * 4]);
        }
        cp_commit();
    };

    float c[2][8][4];
    #pragma unroll
    for (int mi = 0; mi < 2; mi++)
        #pragma unroll
        for (int ni = 0; ni < 8; ni++)
            #pragma unroll
            for (int e = 0; e < 4; e++) c[mi][ni][e] = 0.f;

    int nch = K / TBK;
    issue(0, 0);
    issue(1, 1);

    for (int cc = 0; cc < nch; cc++) {
        if (cc + 1 < nch) cp_wait1(); else cp_wait0();
        __syncthreads();
        if (cc + 2 < nch) issue(cc + 2, (cc + 2) % 3);
        float* As = sm + (cc % 3) * STG;
        float* Bs = As + ASZ;
        #pragma unroll
        for (int ks = 0; ks < 4; ks++) {
            int k0 = ks * 8;
            uint32_t a[2][4], b[8][2];
            #pragma unroll
            for (int mi = 0; mi < 2; mi++) {
                int rb = wm + mi * 16;
                a[mi][0] = __float_as_uint(As[(rb + g)     * ASTR + k0 + tg]);
                a[mi][1] = __float_as_uint(As[(rb + g + 8) * ASTR + k0 + tg]);
                a[mi][2] = __float_as_uint(As[(rb + g)     * ASTR + k0 + tg + 4]);
                a[mi][3] = __float_as_uint(As[(rb + g + 8) * ASTR + k0 + tg + 4]);
            }
            #pragma unroll
            for (int ni = 0; ni < 8; ni++) {
                int col = wn + ni * 8 + g;
                b[ni][0] = __float_as_uint(Bs[(k0 + tg)     * BSTR + col]);
                b[ni][1] = __float_as_uint(Bs[(k0 + tg + 4) * BSTR + col]);
            }
            #pragma unroll
            for (int mi = 0; mi < 2; mi++)
                #pragma unroll
                for (int ni = 0; ni < 8; ni++)
                    mma_tf32_16n8k8(c[mi][ni][0], c[mi][ni][1], c[mi][ni][2], c[mi][ni][3],
                                    a[mi][0], a[mi][1], a[mi][2], a[mi][3],
                                    b[ni][0], b[ni][1]);
        }
        __syncthreads();
    }

    #pragma unroll
    for (int mi = 0; mi < 2; mi++) {
        #pragma unroll
        for (int ni = 0; ni < 8; ni++) {
            int ccol = n0 + wn + ni * 8 + 2 * tg;
            #pragma unroll
            for (int hr = 0; hr < 2; hr++) {
                int r = m0 + wm + mi * 16 + g + hr * 8;
                float v0 = c[mi][ni][hr * 2 + 0];
                float v1 = c[mi][ni][hr * 2 + 1];
                size_t idx = (size_t)r * N + ccol;
                if (EPI == EPI_RES) { v0 += res[idx]; v1 += res[idx + 1]; }
                if (EPI == EPI_BIAS_GELU) {
                    float u0 = v0 + bias[ccol], u1 = v1 + bias[ccol + 1];
                    float z0 = 1.5957691216057308f * (u0 + 0.044715f * u0 * u0 * u0);
                    float z1 = 1.5957691216057308f * (u1 + 0.044715f * u1 * u1 * u1);
                    v0 = to_tf32(__fdividef(u0, 1.f + __expf(-z0)));
                    v1 = to_tf32(__fdividef(u1, 1.f + __expf(-z1)));
                }
                if (EPI == EPI_BIAS_RES) {
                    v0 += bias[ccol]     + res[idx];
                    v1 += bias[ccol + 1] + res[idx + 1];
                }
                if (EPI == EPI_ROUND) { v0 = to_tf32(v0); v1 = to_tf32(v1); }
                *(float2*)&C[idx] = make_float2(v0, v1);
            }
        }
    }
}

template <int EPI>
__global__ __launch_bounds__(256) void gemm_mma(
    const float* __restrict__ A, const float* __restrict__ Bm,
    const float* __restrict__ bias, const float* __restrict__ res,
    float* __restrict__ C, int M, int N, int K)
{
    extern __shared__ float sm[];
    gemm_body<EPI>(A, Bm, bias, res, C, M, N, K,
                   blockIdx.y * TBM, blockIdx.x * TBN, sm);
}

// fused QKV: grid (12, 32). bx<8 -> wq, bx 8-9 -> wk, bx 10-11 -> wv.
__global__ __launch_bounds__(256) void qkv_gemm(
    const float* __restrict__ h,
    const float* __restrict__ wq, const float* __restrict__ wk, const float* __restrict__ wv,
    float* __restrict__ q, float* __restrict__ k, float* __restrict__ v)
{
    extern __shared__ float sm[];
    int bx = blockIdx.x;
    const float* Bm; float* C; int N, n0;
    if (bx < 8)       { Bm = wq; C = q; N = D_;   n0 = bx * 128; }
    else if (bx < 10) { Bm = wk; C = k; N = KVD_; n0 = (bx - 8) * 128; }
    else              { Bm = wv; C = v; N = KVD_; n0 = (bx - 10) * 128; }
    gemm_body<EPI_ROUND>(h, Bm, nullptr, nullptr, C, M_, N, D_,
                         blockIdx.y * TBM, n0, sm);
}

// ---------------- tensor-core causal flash attention (R11 config) -------
#define AQB 128
#define ACB 64
#define KVS 68
#define KVSTG (2 * ACB * KVS)
#define ATTN_SMEM ((2 * KVSTG + 8 * 16 * KVS) * 4)   // 104448 B

__global__ __launch_bounds__(256) void attn_tc(
    const float* __restrict__ Q, const float* __restrict__ Kg,
    const float* __restrict__ Vg, float* __restrict__ O)
{
    extern __shared__ float sm[];
    float* Ps = sm + 2 * KVSTG;

    int tid = threadIdx.x, w = tid >> 5, lane = tid & 31;
    int g = lane >> 2, tg = lane & 3;
    int bx = blockIdx.x, hq = blockIdx.y, b = blockIdx.z;
    int kvh = hq & (HKV_ - 1);
    float* Pw = Ps + w * 16 * KVS;
    uint32_t smb = (uint32_t)__cvta_generic_to_shared(sm);

    int qts[2] = {15 - bx, bx};
    int nts[2] = {2 * (15 - bx) + 2, 2 * bx + 2};
    int total = nts[0] + nts[1];

    auto issue_kv = [&](int i, int st) {
        int kvt = (i < nts[0]) ? i : i - nts[0];
        int kv0 = kvt * ACB;
        uint32_t base = smb + (uint32_t)(st * KVSTG) * 4u;
        #pragma unroll
        for (int t = 0; t < 4; t++) {
            int s = tid + 256 * t;
            int kv = s >> 4, hd4 = (s & 15) * 4;
            size_t gidx = ((size_t)(b * S_ + kv0 + kv)) * KVD_ + kvh * HD_ + hd4;
            cp_async16(base + (uint32_t)(kv * KVS + hd4) * 4u, &Kg[gidx]);
            cp_async16(base + (uint32_t)((ACB + kv) * KVS + hd4) * 4u, &Vg[gidx]);
        }
        cp_commit();
    };

    uint32_t qf[8][4];
    float oc[8][4];
    float m0r, m1r, l0, l1;
    int q0 = qts[0] * AQB;
    int wrow = q0 + w * 16;

    auto load_q = [&]() {
        const float* Qb = Q + ((size_t)(b * S_ + wrow)) * D_ + hq * HD_;
        #pragma unroll
        for (int ks = 0; ks < 8; ks++) {
            qf[ks][0] = __float_as_uint(Qb[(size_t)g       * D_ + ks * 8 + tg]);
            qf[ks][1] = __float_as_uint(Qb[(size_t)(g + 8) * D_ + ks * 8 + tg]);
            qf[ks][2] = __float_as_uint(Qb[(size_t)g       * D_ + ks * 8 + tg + 4]);
            qf[ks][3] = __float_as_uint(Qb[(size_t)(g + 8) * D_ + ks * 8 + tg + 4]);
        }
    };
    auto reset_acc = [&]() {
        #pragma unroll
        for (int ni = 0; ni < 8; ni++)
            #pragma unroll
            for (int e = 0; e < 4; e++) oc[ni][e] = 0.f;
        m0r = -1e30f; m1r = -1e30f; l0 = 0.f; l1 = 0.f;
    };
    auto epilogue = [&]() {
        float il0 = 1.f / l0, il1 = 1.f / l1;
        size_t ob0 = ((size_t)(b * S_ + wrow + g))     * D_ + hq * HD_;
        size_t ob1 = ((size_t)(b * S_ + wrow + g + 8)) * D_ + hq * HD_;
        #pragma unroll
        for (int ni = 0; ni < 8; ni++) {
            int cc = ni * 8 + 2 * tg;
            *(float2*)&O[ob0 + cc] = make_float2(to_tf32(oc[ni][0] * il0), to_tf32(oc[ni][1] * il0));
            *(float2*)&O[ob1 + cc] = make_float2(to_tf32(oc[ni][2] * il1), to_tf32(oc[ni][3] * il1));
        }
    };

    load_q();
    reset_acc();
    issue_kv(0, 0);

    for (int i = 0; i < total; i++) {
        if (i + 1 < total) issue_kv(i + 1, (i + 1) & 1);
        if (i + 1 < total) cp_wait1(); else cp_wait0();
        __syncthreads();

        int kvt = (i < nts[0]) ? i : i - nts[0];
        int kv0 = kvt * ACB;
        float* Ks = sm + (i & 1) * KVSTG;
        float* Vs = Ks + ACB * KVS;

        bool active = (kv0 <= wrow + 15);
        if (active) {
            float sc[8][4];
            #pragma unroll
            for (int ni = 0; ni < 8; ni++)
                #pragma unroll
                for (int e = 0; e < 4; e++) sc[ni][e] = 0.f;
            #pragma unroll
            for (int ks = 0; ks < 8; ks++) {
                #pragma unroll
                for (int ni = 0; ni < 8; ni++) {
                    uint32_t b0 = __float_as_uint(Ks[(ni * 8 + g) * KVS + ks * 8 + tg]);
                    uint32_t b1 = __float_as_uint(Ks[(ni * 8 + g) * KVS + ks * 8 + tg + 4]);
                    mma_tf32_16n8k8(sc[ni][0], sc[ni][1], sc[ni][2], sc[ni][3],
                                    qf[ks][0], qf[ks][1], qf[ks][2], qf[ks][3], b0, b1);
                }
            }
            bool diag = (kv0 + ACB > wrow);
            int r0 = wrow + g, r1 = wrow + g + 8;
            if (diag) {
                #pragma unroll
                for (int ni = 0; ni < 8; ni++) {
                    int c0 = kv0 + ni * 8 + 2 * tg, c1 = c0 + 1;
                    if (c0 > r0) sc[ni][0] = -1e9f;
                    if (c1 > r0) sc[ni][1] = -1e9f;
                    if (c0 > r1) sc[ni][2] = -1e9f;
                    if (c1 > r1) sc[ni][3] = -1e9f;
                }
            }
            float tm0 = -1e30f, tm1 = -1e30f;
            #pragma unroll
            for (int ni = 0; ni < 8; ni++) {
                tm0 = fmaxf(tm0, fmaxf(sc[ni][0], sc[ni][1]));
                tm1 = fmaxf(tm1, fmaxf(sc[ni][2], sc[ni][3]));
            }
            #pragma unroll
            for (int o = 1; o <= 2; o <<= 1) {
                tm0 = fmaxf(tm0, __shfl_xor_sync(0xffffffffu, tm0, o));
                tm1 = fmaxf(tm1, __shfl_xor_sync(0xffffffffu, tm1, o));
            }
            float mn0 = fmaxf(m0r, tm0), mn1 = fmaxf(m1r, tm1);
            float corr0 = __expf(m0r - mn0), corr1 = __expf(m1r - mn1);
            float ps0 = 0.f, ps1 = 0.f;
            #pragma unroll
            for (int ni = 0; ni < 8; ni++) {
                float p0 = __expf(sc[ni][0] - mn0);
                float p1 = __expf(sc[ni][1] - mn0);
                float p2 = __expf(sc[ni][2] - mn1);
                float p3 = __expf(sc[ni][3] - mn1);
                ps0 += p0 + p1; ps1 += p2 + p3;
                int cc = ni * 8 + 2 * tg;
                *(float2*)&Pw[g * KVS + cc]       = make_float2(to_tf32(p0), to_tf32(p1));
                *(float2*)&Pw[(g + 8) * KVS + cc] = make_float2(to_tf32(p2), to_tf32(p3));
            }
            #pragma unroll
            for (int o = 1; o <= 2; o <<= 1) {
                ps0 += __shfl_xor_sync(0xffffffffu, ps0, o);
                ps1 += __shfl_xor_sync(0xffffffffu, ps1, o);
            }
            l0 = l0 * corr0 + ps0; l1 = l1 * corr1 + ps1;
            m0r = mn0; m1r = mn1;
            #pragma unroll
            for (int ni = 0; ni < 8; ni++) {
                oc[ni][0] *= corr0; oc[ni][1] *= corr0;
                oc[ni][2] *= corr1; oc[ni][3] *= corr1;
            }
            __syncwarp();
            #pragma unroll
            for (int ks = 0; ks < 8; ks++) {
                uint32_t a0 = __float_as_uint(Pw[g       * KVS + ks * 8 + tg]);
                uint32_t a1 = __float_as_uint(Pw[(g + 8) * KVS + ks * 8 + tg]);
                uint32_t a2 = __float_as_uint(Pw[g       * KVS + ks * 8 + tg + 4]);
                uint32_t a3 = __float_as_uint(Pw[(g + 8) * KVS + ks * 8 + tg + 4]);
                #pragma unroll
                for (int ni = 0; ni < 8; ni++) {
                    uint32_t b0 = __float_as_uint(Vs[(ks * 8 + tg)     * KVS + ni * 8 + g]);
                    uint32_t b1 = __float_as_uint(Vs[(ks * 8 + tg + 4) * KVS + ni * 8 + g]);
                    mma_tf32_16n8k8(oc[ni][0], oc[ni][1], oc[ni][2], oc[ni][3],
                                    a0, a1, a2, a3, b0, b1);
                }
            }
        }
        __syncthreads();

        if (i == nts[0] - 1) {
            epilogue();
            q0 = qts[1] * AQB;
            wrow = q0 + w * 16;
            load_q();
            reset_acc();
        } else if (i == total - 1) {
            epilogue();
        }
    }
}

// ---------------- launch ----------------
extern "C" void kernel_launch(void* const* d_in, const int* in_sizes, int n_in,
                              void* d_out, int out_size)
{
    const float* x    = (const float*)d_in[0];
    const float* wq   = (const float*)d_in[2];
    const float* wk   = (const float*)d_in[3];
    const float* wv   = (const float*)d_in[4];
    const float* wo   = (const float*)d_in[5];
    const float* ln1g = (const float*)d_in[6];
    const float* ln1b = (const float*)d_in[7];
    const float* ln2g = (const float*)d_in[8];
    const float* ln2b = (const float*)d_in[9];
    const float* w1   = (const float*)d_in[10];
    const float* b1   = (const float*)d_in[11];
    const float* w2   = (const float*)d_in[12];
    const float* b2   = (const float*)d_in[13];
    float* out = (float*)d_out;

    float *h, *q, *k, *v, *o, *x2, *mid;
    float *rwq, *rwk, *rwv, *rwo, *rw1, *rw2;
    cudaGetSymbolAddress((void**)&h,   g_h);
    cudaGetSymbolAddress((void**)&q,   g_q);
    cudaGetSymbolAddress((void**)&k,   g_k);
    cudaGetSymbolAddress((void**)&v,   g_v);
    cudaGetSymbolAddress((void**)&o,   g_o);
    cudaGetSymbolAddress((void**)&x2,  g_x2);
    cudaGetSymbolAddress((void**)&mid, g_mid);
    cudaGetSymbolAddress((void**)&rwq, g_wq);
    cudaGetSymbolAddress((void**)&rwk, g_wk);
    cudaGetSymbolAddress((void**)&rwv, g_wv);
    cudaGetSymbolAddress((void**)&rwo, g_wo);
    cudaGetSymbolAddress((void**)&rw1, g_w1);
    cudaGetSymbolAddress((void**)&rw2, g_w2);

    cudaFuncSetAttribute(attn_tc,  cudaFuncAttributeMaxDynamicSharedMemorySize, ATTN_SMEM);
    cudaFuncSetAttribute(qkv_gemm, cudaFuncAttributeMaxDynamicSharedMemorySize, GEMM_SMEM);
    cudaFuncSetAttribute(gemm_mma<EPI_RES>,       cudaFuncAttributeMaxDynamicSharedMemorySize, GEMM_SMEM);
    cudaFuncSetAttribute(gemm_mma<EPI_BIAS_GELU>, cudaFuncAttributeMaxDynamicSharedMemorySize, GEMM_SMEM);
    cudaFuncSetAttribute(gemm_mma<EPI_BIAS_RES>,  cudaFuncAttributeMaxDynamicSharedMemorySize, GEMM_SMEM);

    // 0. round all weights to tf32 (single launch)
    round_all<<<(RW_N6 + 255) / 256, 256>>>(wq, wk, wv, wo, w1, w2,
                                            rwq, rwk, rwv, rwo, rw1, rw2);

    // 1. h = LN1(x)
    ln_kernel<<<M_, 256>>>(x, ln1g, ln1b, h);
    // 2. fused q/k/v projection
    qkv_gemm<<<dim3(12, M_ / TBM), 256, GEMM_SMEM>>>(h, rwq, rwk, rwv, q, k, v);
    // 3. fused RoPE (q folds 1/8 scale)
    rope_fused<<<(NQI + NKI) / 256, 256>>>(q, k);
    // 4. attention (R11 config)
    attn_tc<<<dim3(8, HQ_, B_), 256, ATTN_SMEM>>>(q, k, v, o);
    // 5. x2 = x + o @ wo
    gemm_mma<EPI_RES><<<dim3(D_ / TBN, M_ / TBM), 256, GEMM_SMEM>>>(o, rwo, nullptr, x, x2, M_, D_, D_);
    // 6. h2 = LN2(x2)
    ln_kernel<<<M_, 256>>>(x2, ln2g, ln2b, h);
    // 7. mid = gelu(h2 @ w1 + b1)
    gemm_mma<EPI_BIAS_GELU><<<dim3(P_ / TBN, M_ / TBM), 256, GEMM_SMEM>>>(h, rw1, b1, nullptr, mid, M_, P_, D_);
    // 8. out = x2 + mid @ w2 + b2
    gemm_mma<EPI_BIAS_RES><<<dim3(D_ / TBN, M_ / TBM), 256, GEMM_SMEM>>>(mid, rw2, b2, x2, out, M_, D_, P_);
}

// round 16
// speedup vs baseline: 1.1820x; 1.0144x over previous
#include <cuda_runtime.h>
#include <math.h>
#include <stdint.h>

// ---------------- problem constants ----------------
#define B_   2
#define S_   2048
#define D_   1024
#define HQ_  16
#define HKV_ 4
#define HD_  64
#define P_   4096
#define M_   (B_ * S_)        // 4096
#define KVD_ (HKV_ * HD_)     // 256

// ---------------- scratch ----------------
__device__ float g_h [M_ * D_];
__device__ float g_q [M_ * D_];
__device__ float g_k [M_ * KVD_];
__device__ float g_v [M_ * KVD_];
__device__ float g_o [M_ * D_];
__device__ float g_x2[M_ * D_];
__device__ float g_mid[M_ * P_];
// tf32-rounded weights
__device__ float g_wq[D_ * D_];
__device__ float g_wk[D_ * KVD_];
__device__ float g_wv[D_ * KVD_];
__device__ float g_wo[D_ * D_];
__device__ float g_w1[D_ * P_];
__device__ float g_w2[P_ * D_];

__device__ __forceinline__ float to_tf32(float x) {
    float r; asm("cvt.rna.tf32.f32 %0, %1;" : "=f"(r) : "f"(x)); return r;
}

__device__ __forceinline__ void mma_tf32_16n8k8(
    float& d0, float& d1, float& d2, float& d3,
    uint32_t a0, uint32_t a1, uint32_t a2, uint32_t a3,
    uint32_t b0, uint32_t b1)
{
    asm volatile(
        "mma.sync.aligned.m16n8k8.row.col.f32.tf32.tf32.f32 "
        "{%0,%1,%2,%3}, {%4,%5,%6,%7}, {%8,%9}, {%0,%1,%2,%3};"
        : "+f"(d0), "+f"(d1), "+f"(d2), "+f"(d3)
        : "r"(a0), "r"(a1), "r"(a2), "r"(a3), "r"(b0), "r"(b1));
}

__device__ __forceinline__ void cp_async16(uint32_t s, const void* g) {
    asm volatile("cp.async.cg.shared.global [%0], [%1], 16;" :: "r"(s), "l"(g));
}
__device__ __forceinline__ void cp_commit() { asm volatile("cp.async.commit_group;" ::: "memory"); }
__device__ __forceinline__ void cp_wait0()  { asm volatile("cp.async.wait_group 0;" ::: "memory"); }
__device__ __forceinline__ void cp_wait1()  { asm volatile("cp.async.wait_group 1;" ::: "memory"); }

// ---------------- weight rounding: single launch over all 6 weights -----
#define RW_N1 (D_ * D_ / 4)
#define RW_N2 (RW_N1 + D_ * KVD_ / 4)
#define RW_N3 (RW_N2 + D_ * KVD_ / 4)
#define RW_N4 (RW_N3 + D_ * D_ / 4)
#define RW_N5 (RW_N4 + D_ * P_ / 4)
#define RW_N6 (RW_N5 + P_ * D_ / 4)
__global__ __launch_bounds__(256) void round_all(
    const float* __restrict__ wq, const float* __restrict__ wk,
    const float* __restrict__ wv, const float* __restrict__ wo,
    const float* __restrict__ w1, const float* __restrict__ w2,
    float* __restrict__ rwq, float* __restrict__ rwk,
    float* __restrict__ rwv, float* __restrict__ rwo,
    float* __restrict__ rw1, float* __restrict__ rw2)
{
    int i = blockIdx.x * blockDim.x + threadIdx.x;
    if (i >= RW_N6) return;
    const float* s; float* d; int off;
    if      (i < RW_N1) { s = wq; d = rwq; off = 0; }
    else if (i < RW_N2) { s = wk; d = rwk; off = RW_N1; }
    else if (i < RW_N3) { s = wv; d = rwv; off = RW_N2; }
    else if (i < RW_N4) { s = wo; d = rwo; off = RW_N3; }
    else if (i < RW_N5) { s = w1; d = rw1; off = RW_N4; }
    else                { s = w2; d = rw2; off = RW_N5; }
    int j = i - off;
    float4 v = *(const float4*)&s[(size_t)j * 4];
    v.x = to_tf32(v.x); v.y = to_tf32(v.y); v.z = to_tf32(v.z); v.w = to_tf32(v.w);
    *(float4*)&d[(size_t)j * 4] = v;
}

// ---------------- LayerNorm (tf32-rounded output) ----------------
__global__ __launch_bounds__(256) void ln_kernel(
    const float* __restrict__ x, const float* __restrict__ gam,
    const float* __restrict__ bet, float* __restrict__ out)
{
    __shared__ float red[20];
    int row = blockIdx.x;
    int tid = threadIdx.x;
    const float* xr = x + (size_t)row * D_;
    float4 v = *(const float4*)&xr[tid * 4];
    float s  = v.x + v.y + v.z + v.w;
    float sq = v.x * v.x + v.y * v.y + v.z * v.z + v.w * v.w;
    #pragma unroll
    for (int o = 16; o; o >>= 1) {
        s  += __shfl_xor_sync(0xffffffffu, s,  o);
        sq += __shfl_xor_sync(0xffffffffu, sq, o);
    }
    if ((tid & 31) == 0) { red[tid >> 5] = s; red[8 + (tid >> 5)] = sq; }
    __syncthreads();
    if (tid < 32) {
        float a = (tid < 8) ? red[tid]     : 0.f;
        float b = (tid < 8) ? red[8 + tid] : 0.f;
        #pragma unroll
        for (int o = 4; o; o >>= 1) {
            a += __shfl_xor_sync(0xffffffffu, a, o);
            b += __shfl_xor_sync(0xffffffffu, b, o);
        }
        if (tid == 0) { red[16] = a; red[17] = b; }
    }
    __syncthreads();
    float mean = red[16] * (1.f / D_);
    float var  = red[17] * (1.f / D_) - mean * mean;
    float rs   = rsqrtf(var + 1e-5f);
    float4 gv = *(const float4*)&gam[tid * 4];
    float4 bv = *(const float4*)&bet[tid * 4];
    float4 ov;
    ov.x = to_tf32((v.x - mean) * rs * gv.x + bv.x);
    ov.y = to_tf32((v.y - mean) * rs * gv.y + bv.y);
    ov.z = to_tf32((v.z - mean) * rs * gv.z + bv.z);
    ov.w = to_tf32((v.w - mean) * rs * gv.w + bv.w);
    *(float4*)&out[(size_t)row * D_ + tid * 4] = ov;
}

// ---------------- cp.async 3-stage tf32 GEMM (R8 config, frozen) --------
#define TBM 128
#define TBN 128
#define TBK 32
#define ASTR 36
#define BSTR 136
#define ASZ (TBM * ASTR)
#define BSZ (TBK * BSTR)
#define STG (ASZ + BSZ)
#define GEMM_SMEM (3 * STG * 4)    // 107520 B

enum { EPI_NONE = 0, EPI_RES = 1, EPI_BIAS_GELU = 2, EPI_BIAS_RES = 3, EPI_ROUND = 4, EPI_ROPE = 5 };

template <int EPI>
__device__ __forceinline__ void gemm_body(
    const float* __restrict__ A, const float* __restrict__ Bm,
    const float* __restrict__ bias, const float* __restrict__ res,
    float* __restrict__ C, int M, int N, int K, int m0, int n0, float* sm,
    float ropesc = 1.0f)
{
    int tid = threadIdx.x;
    int wid = tid >> 5, lane = tid & 31;
    int g = lane >> 2, tg = lane & 3;
    int wm = (wid & 3) * 32, wn = (wid >> 2) * 64;
    uint32_t smb = (uint32_t)__cvta_generic_to_shared(sm);

    auto issue = [&](int kc, int st) {
        int k0 = kc * TBK;
        uint32_t ab = smb + (uint32_t)(st * STG) * 4u;
        uint32_t bb = ab + ASZ * 4u;
        #pragma unroll
        for (int t = 0; t < 4; t++) {
            int i = tid + 256 * t;
            int mm = i >> 3, kq = i & 7;
            cp_async16(ab + (uint32_t)(mm * ASTR + kq * 4) * 4u,
                       &A[(size_t)(m0 + mm) * K + k0 + kq * 4]);
            int kk = i >> 5, nq = i & 31;
            cp_async16(bb + (uint32_t)(kk * BSTR + nq * 4) * 4u,
                       &Bm[(size_t)(k0 + kk) * N + n0 + nq * 4]);
        }
        cp_commit();
    };

    float c[2][8][4];
    #pragma unroll
    for (int mi = 0; mi < 2; mi++)
        #pragma unroll
        for (int ni = 0; ni < 8; ni++)
            #pragma unroll
            for (int e = 0; e < 4; e++) c[mi][ni][e] = 0.f;

    int nch = K / TBK;
    issue(0, 0);
    issue(1, 1);

    for (int cc = 0; cc < nch; cc++) {
        if (cc + 1 < nch) cp_wait1(); else cp_wait0();
        __syncthreads();
        if (cc + 2 < nch) issue(cc + 2, (cc + 2) % 3);
        float* As = sm + (cc % 3) * STG;
        float* Bs = As + ASZ;
        #pragma unroll
        for (int ks = 0; ks < 4; ks++) {
            int k0 = ks * 8;
            uint32_t a[2][4], b[8][2];
            #pragma unroll
            for (int mi = 0; mi < 2; mi++) {
                int rb = wm + mi * 16;
                a[mi][0] = __float_as_uint(As[(rb + g)     * ASTR + k0 + tg]);
                a[mi][1] = __float_as_uint(As[(rb + g + 8) * ASTR + k0 + tg]);
                a[mi][2] = __float_as_uint(As[(rb + g)     * ASTR + k0 + tg + 4]);
                a[mi][3] = __float_as_uint(As[(rb + g + 8) * ASTR + k0 + tg + 4]);
            }
            #pragma unroll
            for (int ni = 0; ni < 8; ni++) {
                int col = wn + ni * 8 + g;
                b[ni][0] = __float_as_uint(Bs[(k0 + tg)     * BSTR + col]);
                b[ni][1] = __float_as_uint(Bs[(k0 + tg + 4) * BSTR + col]);
            }
            #pragma unroll
            for (int mi = 0; mi < 2; mi++)
                #pragma unroll
                for (int ni = 0; ni < 8; ni++)
                    mma_tf32_16n8k8(c[mi][ni][0], c[mi][ni][1], c[mi][ni][2], c[mi][ni][3],
                                    a[mi][0], a[mi][1], a[mi][2], a[mi][3],
                                    b[ni][0], b[ni][1]);
        }
        __syncthreads();
    }

    if (EPI == EPI_ROPE) {
        // paired rotary epilogue: c[mi][ni] / c[mi][ni+4] (ni<4) are head cols
        // (j, j+32) with j = ni*8+2tg. Apply rope in-register, round, store.
        #pragma unroll
        for (int mi = 0; mi < 2; mi++) {
            #pragma unroll
            for (int hr = 0; hr < 2; hr++) {
                int r = m0 + wm + mi * 16 + g + hr * 8;
                float srow = (float)(r & (S_ - 1));
                #pragma unroll
                for (int ni = 0; ni < 4; ni++) {
                    int ccol = n0 + wn + ni * 8 + 2 * tg;
                    int j0 = ccol & 63;                 // = ni*8+2tg, < 32
                    float inv0 = exp2f(-(float)j0 * (13.287712379549449f / 32.f));
                    float inv1 = exp2f(-(float)(j0 + 1) * (13.287712379549449f / 32.f));
                    float sn0, cs0, sn1, cs1;
                    sincosf(srow * inv0, &sn0, &cs0);
                    sincosf(srow * inv1, &sn1, &cs1);
                    float x1a = c[mi][ni][hr * 2 + 0],     x1b = c[mi][ni][hr * 2 + 1];
                    float x2a = c[mi][ni + 4][hr * 2 + 0], x2b = c[mi][ni + 4][hr * 2 + 1];
                    float lo0 = (x1a * cs0 - x2a * sn0) * ropesc;
                    float lo1 = (x1b * cs1 - x2b * sn1) * ropesc;
                    float hi0 = (x1a * sn0 + x2a * cs0) * ropesc;
                    float hi1 = (x1b * sn1 + x2b * cs1) * ropesc;
                    size_t idx = (size_t)r * N + ccol;
                    *(float2*)&C[idx]      = make_float2(to_tf32(lo0), to_tf32(lo1));
                    *(float2*)&C[idx + 32] = make_float2(to_tf32(hi0), to_tf32(hi1));
                }
            }
        }
        return;
    }

    #pragma unroll
    for (int mi = 0; mi < 2; mi++) {
        #pragma unroll
        for (int ni = 0; ni < 8; ni++) {
            int ccol = n0 + wn + ni * 8 + 2 * tg;
            #pragma unroll
            for (int hr = 0; hr < 2; hr++) {
                int r = m0 + wm + mi * 16 + g + hr * 8;
                float v0 = c[mi][ni][hr * 2 + 0];
                float v1 = c[mi][ni][hr * 2 + 1];
                size_t idx = (size_t)r * N + ccol;
                if (EPI == EPI_RES) { v0 += res[idx]; v1 += res[idx + 1]; }
                if (EPI == EPI_BIAS_GELU) {
                    float u0 = v0 + bias[ccol], u1 = v1 + bias[ccol + 1];
                    float z0 = 1.5957691216057308f * (u0 + 0.044715f * u0 * u0 * u0);
                    float z1 = 1.5957691216057308f * (u1 + 0.044715f * u1 * u1 * u1);
                    v0 = to_tf32(__fdividef(u0, 1.f + __expf(-z0)));
                    v1 = to_tf32(__fdividef(u1, 1.f + __expf(-z1)));
                }
                if (EPI == EPI_BIAS_RES) {
                    v0 += bias[ccol]     + res[idx];
                    v1 += bias[ccol + 1] + res[idx + 1];
                }
                if (EPI == EPI_ROUND) { v0 = to_tf32(v0); v1 = to_tf32(v1); }
                *(float2*)&C[idx] = make_float2(v0, v1);
            }
        }
    }
}

template <int EPI>
__global__ __launch_bounds__(256) void gemm_mma(
    const float* __restrict__ A, const float* __restrict__ Bm,
    const float* __restrict__ bias, const float* __restrict__ res,
    float* __restrict__ C, int M, int N, int K)
{
    extern __shared__ float sm[];
    gemm_body<EPI>(A, Bm, bias, res, C, M, N, K,
                   blockIdx.y * TBM, blockIdx.x * TBN, sm);
}

// fused QKV + RoPE: grid (12, 32). bx<8 -> wq (rope, scale 0.125*log2e),
// bx 8-9 -> wk (rope, scale 1), bx 10-11 -> wv (plain round).
#define QSCALE (0.125f * 1.4426950408889634f)
__global__ __launch_bounds__(256) void qkv_gemm(
    const float* __restrict__ h,
    const float* __restrict__ wq, const float* __restrict__ wk, const float* __restrict__ wv,
    float* __restrict__ q, float* __restrict__ k, float* __restrict__ v)
{
    extern __shared__ float sm[];
    int bx = blockIdx.x;
    if (bx < 8) {
        gemm_body<EPI_ROPE>(h, wq, nullptr, nullptr, q, M_, D_, D_,
                            blockIdx.y * TBM, bx * 128, sm, QSCALE);
    } else if (bx < 10) {
        gemm_body<EPI_ROPE>(h, wk, nullptr, nullptr, k, M_, KVD_, D_,
                            blockIdx.y * TBM, (bx - 8) * 128, sm, 1.0f);
    } else {
        gemm_body<EPI_ROUND>(h, wv, nullptr, nullptr, v, M_, KVD_, D_,
                             blockIdx.y * TBM, (bx - 10) * 128, sm);
    }
}

// ---------------- tensor-core causal flash attention (R11 config) -------
// q carries 0.125*log2e scale -> softmax in exp2 domain (bare EX2).
#define AQB 128
#define ACB 64
#define KVS 68
#define KVSTG (2 * ACB * KVS)
#define ATTN_SMEM ((2 * KVSTG + 8 * 16 * KVS) * 4)   // 104448 B

__global__ __launch_bounds__(256) void attn_tc(
    const float* __restrict__ Q, const float* __restrict__ Kg,
    const float* __restrict__ Vg, float* __restrict__ O)
{
    extern __shared__ float sm[];
    float* Ps = sm + 2 * KVSTG;

    int tid = threadIdx.x, w = tid >> 5, lane = tid & 31;
    int g = lane >> 2, tg = lane & 3;
    int bx = blockIdx.x, hq = blockIdx.y, b = blockIdx.z;
    int kvh = hq & (HKV_ - 1);
    float* Pw = Ps + w * 16 * KVS;
    uint32_t smb = (uint32_t)__cvta_generic_to_shared(sm);

    int qts[2] = {15 - bx, bx};
    int nts[2] = {2 * (15 - bx) + 2, 2 * bx + 2};
    int total = nts[0] + nts[1];

    auto issue_kv = [&](int i, int st) {
        int kvt = (i < nts[0]) ? i : i - nts[0];
        int kv0 = kvt * ACB;
        uint32_t base = smb + (uint32_t)(st * KVSTG) * 4u;
        #pragma unroll
        for (int t = 0; t < 4; t++) {
            int s = tid + 256 * t;
            int kv = s >> 4, hd4 = (s & 15) * 4;
            size_t gidx = ((size_t)(b * S_ + kv0 + kv)) * KVD_ + kvh * HD_ + hd4;
            cp_async16(base + (uint32_t)(kv * KVS + hd4) * 4u, &Kg[gidx]);
            cp_async16(base + (uint32_t)((ACB + kv) * KVS + hd4) * 4u, &Vg[gidx]);
        }
        cp_commit();
    };

    uint32_t qf[8][4];
    float oc[8][4];
    float m0r, m1r, l0, l1;
    int q0 = qts[0] * AQB;
    int wrow = q0 + w * 16;

    auto load_q = [&]() {
        const float* Qb = Q + ((size_t)(b * S_ + wrow)) * D_ + hq * HD_;
        #pragma unroll
        for (int ks = 0; ks < 8; ks++) {
            qf[ks][0] = __float_as_uint(Qb[(size_t)g       * D_ + ks * 8 + tg]);
            qf[ks][1] = __float_as_uint(Qb[(size_t)(g + 8) * D_ + ks * 8 + tg]);
            qf[ks][2] = __float_as_uint(Qb[(size_t)g       * D_ + ks * 8 + tg + 4]);
            qf[ks][3] = __float_as_uint(Qb[(size_t)(g + 8) * D_ + ks * 8 + tg + 4]);
        }
    };
    auto reset_acc = [&]() {
        #pragma unroll
        for (int ni = 0; ni < 8; ni++)
            #pragma unroll
            for (int e = 0; e < 4; e++) oc[ni][e] = 0.f;
        m0r = -1e30f; m1r = -1e30f; l0 = 0.f; l1 = 0.f;
    };
    auto epilogue = [&]() {
        float il0 = 1.f / l0, il1 = 1.f / l1;
        size_t ob0 = ((size_t)(b * S_ + wrow + g))     * D_ + hq * HD_;
        size_t ob1 = ((size_t)(b * S_ + wrow + g + 8)) * D_ + hq * HD_;
        #pragma unroll
        for (int ni = 0; ni < 8; ni++) {
            int cc = ni * 8 + 2 * tg;
            *(float2*)&O[ob0 + cc] = make_float2(to_tf32(oc[ni][0] * il0), to_tf32(oc[ni][1] * il0));
            *(float2*)&O[ob1 + cc] = make_float2(to_tf32(oc[ni][2] * il1), to_tf32(oc[ni][3] * il1));
        }
    };

    load_q();
    reset_acc();
    issue_kv(0, 0);

    for (int i = 0; i < total; i++) {
        if (i + 1 < total) issue_kv(i + 1, (i + 1) & 1);
        if (i + 1 < total) cp_wait1(); else cp_wait0();
        __syncthreads();

        int kvt = (i < nts[0]) ? i : i - nts[0];
        int kv0 = kvt * ACB;
        float* Ks = sm + (i & 1) * KVSTG;
        float* Vs = Ks + ACB * KVS;

        bool active = (kv0 <= wrow + 15);
        if (active) {
            float sc[8][4];
            #pragma unroll
            for (int ni = 0; ni < 8; ni++)
                #pragma unroll
                for (int e = 0; e < 4; e++) sc[ni][e] = 0.f;
            #pragma unroll
            for (int ks = 0; ks < 8; ks++) {
                #pragma unroll
                for (int ni = 0; ni < 8; ni++) {
                    uint32_t b0 = __float_as_uint(Ks[(ni * 8 + g) * KVS + ks * 8 + tg]);
                    uint32_t b1 = __float_as_uint(Ks[(ni * 8 + g) * KVS + ks * 8 + tg + 4]);
                    mma_tf32_16n8k8(sc[ni][0], sc[ni][1], sc[ni][2], sc[ni][3],
                                    qf[ks][0], qf[ks][1], qf[ks][2], qf[ks][3], b0, b1);
                }
            }
            bool diag = (kv0 + ACB > wrow);
            int r0 = wrow + g, r1 = wrow + g + 8;
            if (diag) {
                #pragma unroll
                for (int ni = 0; ni < 8; ni++) {
                    int c0 = kv0 + ni * 8 + 2 * tg, c1 = c0 + 1;
                    if (c0 > r0) sc[ni][0] = -1e9f;
                    if (c1 > r0) sc[ni][1] = -1e9f;
                    if (c0 > r1) sc[ni][2] = -1e9f;
                    if (c1 > r1) sc[ni][3] = -1e9f;
                }
            }
            float tm0 = -1e30f, tm1 = -1e30f;
            #pragma unroll
            for (int ni = 0; ni < 8; ni++) {
                tm0 = fmaxf(tm0, fmaxf(sc[ni][0], sc[ni][1]));
                tm1 = fmaxf(tm1, fmaxf(sc[ni][2], sc[ni][3]));
            }
            #pragma unroll
            for (int o = 1; o <= 2; o <<= 1) {
                tm0 = fmaxf(tm0, __shfl_xor_sync(0xffffffffu, tm0, o));
                tm1 = fmaxf(tm1, __shfl_xor_sync(0xffffffffu, tm1, o));
            }
            float mn0 = fmaxf(m0r, tm0), mn1 = fmaxf(m1r, tm1);
            float corr0 = exp2f(m0r - mn0), corr1 = exp2f(m1r - mn1);
            float ps0 = 0.f, ps1 = 0.f;
            #pragma unroll
            for (int ni = 0; ni < 8; ni++) {
                float p0 = exp2f(sc[ni][0] - mn0);
                float p1 = exp2f(sc[ni][1] - mn0);
                float p2 = exp2f(sc[ni][2] - mn1);
                float p3 = exp2f(sc[ni][3] - mn1);
                ps0 += p0 + p1; ps1 += p2 + p3;
                int cc = ni * 8 + 2 * tg;
                *(float2*)&Pw[g * KVS + cc]       = make_float2(to_tf32(p0), to_tf32(p1));
                *(float2*)&Pw[(g + 8) * KVS + cc] = make_float2(to_tf32(p2), to_tf32(p3));
            }
            #pragma unroll
            for (int o = 1; o <= 2; o <<= 1) {
                ps0 += __shfl_xor_sync(0xffffffffu, ps0, o);
                ps1 += __shfl_xor_sync(0xffffffffu, ps1, o);
            }
            l0 = l0 * corr0 + ps0; l1 = l1 * corr1 + ps1;
            m0r = mn0; m1r = mn1;
            #pragma unroll
            for (int ni = 0; ni < 8; ni++) {
                oc[ni][0] *= corr0; oc[ni][1] *= corr0;
                oc[ni][2] *= corr1; oc[ni][3] *= corr1;
            }
            __syncwarp();
            #pragma unroll
            for (int ks = 0; ks < 8; ks++) {
                uint32_t a0 = __float_as_uint(Pw[g       * KVS + ks * 8 + tg]);
                uint32_t a1 = __float_as_uint(Pw[(g + 8) * KVS + ks * 8 + tg]);
                uint32_t a2 = __float_as_uint(Pw[g       * KVS + ks * 8 + tg + 4]);
                uint32_t a3 = __float_as_uint(Pw[(g + 8) * KVS + ks * 8 + tg + 4]);
                #pragma unroll
                for (int ni = 0; ni < 8; ni++) {
                    uint32_t b0 = __float_as_uint(Vs[(ks * 8 + tg)     * KVS + ni * 8 + g]);
                    uint32_t b1 = __float_as_uint(Vs[(ks * 8 + tg + 4) * KVS + ni * 8 + g]);
                    mma_tf32_16n8k8(oc[ni][0], oc[ni][1], oc[ni][2], oc[ni][3],
                                    a0, a1, a2, a3, b0, b1);
                }
            }
        }
        __syncthreads();

        if (i == nts[0] - 1) {
            epilogue();
            q0 = qts[1] * AQB;
            wrow = q0 + w * 16;
            load_q();
            reset_acc();
        } else if (i == total - 1) {
            epilogue();
        }
    }
}

// ---------------- launch ----------------
extern "C" void kernel_launch(void* const* d_in, const int* in_sizes, int n_in,
                              void* d_out, int out_size)
{
    const float* x    = (const float*)d_in[0];
    const float* wq   = (const float*)d_in[2];
    const float* wk   = (const float*)d_in[3];
    const float* wv   = (const float*)d_in[4];
    const float* wo   = (const float*)d_in[5];
    const float* ln1g = (const float*)d_in[6];
    const float* ln1b = (const float*)d_in[7];
    const float* ln2g = (const float*)d_in[8];
    const float* ln2b = (const float*)d_in[9];
    const float* w1   = (const float*)d_in[10];
    const float* b1   = (const float*)d_in[11];
    const float* w2   = (const float*)d_in[12];
    const float* b2   = (const float*)d_in[13];
    float* out = (float*)d_out;

    float *h, *q, *k, *v, *o, *x2, *mid;
    float *rwq, *rwk, *rwv, *rwo, *rw1, *rw2;
    cudaGetSymbolAddress((void**)&h,   g_h);
    cudaGetSymbolAddress((void**)&q,   g_q);
    cudaGetSymbolAddress((void**)&k,   g_k);
    cudaGetSymbolAddress((void**)&v,   g_v);
    cudaGetSymbolAddress((void**)&o,   g_o);
    cudaGetSymbolAddress((void**)&x2,  g_x2);
    cudaGetSymbolAddress((void**)&mid, g_mid);
    cudaGetSymbolAddress((void**)&rwq, g_wq);
    cudaGetSymbolAddress((void**)&rwk, g_wk);
    cudaGetSymbolAddress((void**)&rwv, g_wv);
    cudaGetSymbolAddress((void**)&rwo, g_wo);
    cudaGetSymbolAddress((void**)&rw1, g_w1);
    cudaGetSymbolAddress((void**)&rw2, g_w2);

    cudaFuncSetAttribute(attn_tc,  cudaFuncAttributeMaxDynamicSharedMemorySize, ATTN_SMEM);
    cudaFuncSetAttribute(qkv_gemm, cudaFuncAttributeMaxDynamicSharedMemorySize, GEMM_SMEM);
    cudaFuncSetAttribute(gemm_mma<EPI_RES>,       cudaFuncAttributeMaxDynamicSharedMemorySize, GEMM_SMEM);
    cudaFuncSetAttribute(gemm_mma<EPI_BIAS_GELU>, cudaFuncAttributeMaxDynamicSharedMemorySize, GEMM_SMEM);
    cudaFuncSetAttribute(gemm_mma<EPI_BIAS_RES>,  cudaFuncAttributeMaxDynamicSharedMemorySize, GEMM_SMEM);

    // 0. round all weights to tf32 (single launch)
    round_all<<<(RW_N6 + 255) / 256, 256>>>(wq, wk, wv, wo, w1, w2,
                                            rwq, rwk, rwv, rwo, rw1, rw2);

    // 1. h = LN1(x)
    ln_kernel<<<M_, 256>>>(x, ln1g, ln1b, h);
    // 2. fused q/k/v projection + RoPE (q folds 0.125*log2e)
    qkv_gemm<<<dim3(12, M_ / TBM), 256, GEMM_SMEM>>>(h, rwq, rwk, rwv, q, k, v);
    // 3. attention (softmax in exp2 domain)
    attn_tc<<<dim3(8, HQ_, B_), 256, ATTN_SMEM>>>(q, k, v, o);
    // 4. x2 = x + o @ wo
    gemm_mma<EPI_RES><<<dim3(D_ / TBN, M_ / TBM), 256, GEMM_SMEM>>>(o, rwo, nullptr, x, x2, M_, D_, D_);
    // 5. h2 = LN2(x2)
    ln_kernel<<<M_, 256>>>(x2, ln2g, ln2b, h);
    // 6. mid = gelu(h2 @ w1 + b1)
    gemm_mma<EPI_BIAS_GELU><<<dim3(P_ / TBN, M_ / TBM), 256, GEMM_SMEM>>>(h, rw1, b1, nullptr, mid, M_, P_, D_);
    // 7. out = x2 + mid @ w2 + b2
    gemm_mma<EPI_BIAS_RES><<<dim3(D_ / TBN, M_ / TBM), 256, GEMM_SMEM>>>(mid, rw2, b2, x2, out, M_, D_, P_);
}